// round 17
// baseline (speedup 1.0000x reference)
#include <cuda_runtime.h>
#include <cuda_fp16.h>
#include <math.h>
#include <cstdint>

#define NN 50000
#define EE 800000
#define DD 64

typedef unsigned long long u64;

// ---------------- scratch (static device globals; no runtime allocation) ----
__device__ __align__(16) float g_esrc[NN*DD];
__device__ __align__(16) float g_edst[NN*DD];
__device__ __align__(16) float g_Bh[NN*DD];
__device__ __align__(16) float g_xs[NN*DD];      // xs, then x_pre in-place
__device__ __align__(16) __half g_mh[EE*DD];     // m stored fp16 (102.4 MB)
__device__ __align__(16) float g_sumh[NN*DD];
__device__ __align__(16) float g_sums[NN*DD];
// stats: [0..63] e_sum, [64..127] e_sumsq, [128..191] n_sum, [192..255] n_sumsq
__device__ __align__(16) float g_stats[256];

__device__ __forceinline__ float fsilu(float z) { return z / (1.f + __expf(-z)); }
__device__ __forceinline__ unsigned h2bits(__half2 h) { return *(unsigned*)&h; }

// fast sigmoid: sigma(x) = 0.5*tanh(x/2) + 0.5  (1 MUFU + 2 fma; used in
// k_edge where sigma feeds sum ratios -> approx error largely cancels)
__device__ __forceinline__ float fsigmoid_fast(float x) {
    float t;
    asm("tanh.approx.f32 %0, %1;" : "=f"(t) : "f"(x * 0.5f));
    return fmaf(t, 0.5f, 0.5f);
}

// vectorized no-return fp32 reduction: 1 instruction, 16 bytes, 4 lanes
__device__ __forceinline__ void red_add_v4(float* addr, float a, float b, float c, float d) {
    asm volatile("red.global.add.v4.f32 [%0], {%1,%2,%3,%4};"
                 :: "l"(addr), "f"(a), "f"(b), "f"(c), "f"(d) : "memory");
}

// warp-level tensor-core mma (baseline PTX, valid on sm_103 non-'a' target)
__device__ __forceinline__ void mma_16816(float* c, uint32_t a0, uint32_t a1,
                                          uint32_t a2, uint32_t a3,
                                          uint32_t b0, uint32_t b1) {
    asm volatile(
        "mma.sync.aligned.m16n8k16.row.col.f32.f16.f16.f32 "
        "{%0,%1,%2,%3}, {%4,%5,%6,%7}, {%8,%9}, {%0,%1,%2,%3};"
        : "+f"(c[0]), "+f"(c[1]), "+f"(c[2]), "+f"(c[3])
        : "r"(a0), "r"(a1), "r"(a2), "r"(a3), "r"(b0), "r"(b1));
}

// k_edge smem byte offsets (dynamic smem, 48128 B total -> 4 blocks/SM)
#define SM_IDX  0         // 256 ints (1024 B)
#define SM_SRED 1024      // 256 floats (1024 B)
#define SM_W    2048      // 64 rows x 72 halves packed  (9216 B)
#define SM_A    11264     // 128 rows x 72 halves        (18432 B)
#define SM_D    29696     // 128 rows x 72 halves (fp16 D stage, 18432 B)
#define SM_EDGE_TOTAL 48128

// k_node_gemm smem byte offsets (90112 B -> 2 blocks/SM)
#define NG_W    0         // 4 matrices x 64 x 72 halves (36864 B)
#define NG_A    36864     // 128 x 72 halves             (18432 B)
#define NG_D    55296     // 128 x 68 floats             (34816 B)
#define NG_TOTAL 90112

// ---------------- K1: node GEMMs via mma.sync (e_src, e_dst, Bh, xs) --------
__global__ void __launch_bounds__(256, 2) k_node_gemm(
    const float* __restrict__ nf,
    const float* __restrict__ Wsg, const float* __restrict__ bsg,
    const float* __restrict__ Wdg, const float* __restrict__ bdg,
    const float* __restrict__ Wdu, const float* __restrict__ bdu,
    const float* __restrict__ Wsu, const float* __restrict__ bsu)
{
    extern __shared__ char smem[];
    __half* sW = (__half*)(smem + NG_W);
    __half* sA = (__half*)(smem + NG_A);
    float*  sD = (float*)(smem + NG_D);

    int tid = threadIdx.x;
    int wid = tid >> 5, lane = tid & 31;
    int tig = lane & 3, grp = lane >> 2;
    int tx = tid & 15, ty = tid >> 4;

    if (blockIdx.x == 0) g_stats[tid] = 0.f;

    // pack all 4 weight matrices (k_edge layout per matrix)
    #pragma unroll
    for (int jm = 0; jm < 4; jm++) {
        const float* Wp = (jm == 0) ? Wsg : (jm == 1) ? Wdg : (jm == 2) ? Wdu : Wsu;
        for (int i = tid; i < 4096; i += 256) {
            int k = i >> 6, n = i & 63;
            int s = k >> 4, r = k & 15;
            int q = (r & 7) >> 1, hi = r >> 3, lo = r & 1;
            sW[jm*4608 + n*72 + s*16 + q*4 + hi*2 + lo] = __float2half_rn(Wp[i]);
        }
    }
    float4 bb[4];
    bb[0] = *(const float4*)(bsg + tx*4);
    bb[1] = *(const float4*)(bdg + tx*4);
    bb[2] = *(const float4*)(bdu + tx*4);
    bb[3] = *(const float4*)(bsu + tx*4);

    int nchunk = (NN + 127) / 128;        // 391
    for (int c = blockIdx.x; c < nchunk; c += gridDim.x) {
        int base = c * 128;
        __syncthreads();                  // prev chunk's last epilogue done
        #pragma unroll
        for (int l = 0; l < 8; l++) {
            int idx = tid + l * 256;
            int r = idx >> 4, c4 = (idx & 15) * 4;
            int row = base + r;
            float4 v = make_float4(0.f, 0.f, 0.f, 0.f);
            if (row < NN) v = *(const float4*)(nf + row*64 + c4);
            __half2 h0 = __floats2half2_rn(v.x, v.y);
            __half2 h1 = __floats2half2_rn(v.z, v.w);
            *(uint2*)(sA + r*72 + c4) = make_uint2(h2bits(h0), h2bits(h1));
        }
        __syncthreads();

        #pragma unroll
        for (int jm = 0; jm < 4; jm++) {
            float acc[8][4];
            #pragma unroll
            for (int j = 0; j < 8; j++) {
                acc[j][0] = 0.f; acc[j][1] = 0.f; acc[j][2] = 0.f; acc[j][3] = 0.f;
            }
            const __half* arow  = sA + (wid*16 + grp)*72;
            const __half* wbase = sW + jm*4608;
            #pragma unroll
            for (int s = 0; s < 4; s++) {
                int k0 = s*16 + tig*2;
                uint32_t a0 = *(const uint32_t*)(arow + k0);
                uint32_t a1 = *(const uint32_t*)(arow + 8*72 + k0);
                uint32_t a2 = *(const uint32_t*)(arow + k0 + 8);
                uint32_t a3 = *(const uint32_t*)(arow + 8*72 + k0 + 8);
                #pragma unroll
                for (int j = 0; j < 8; j++) {
                    uint2 b = *(const uint2*)(wbase + (j*8 + grp)*72 + s*16 + tig*4);
                    mma_16816(acc[j], a0, a1, a2, a3, b.x, b.y);
                }
            }

            // stage D (fp32) to smem
            float* drow = sD + (wid*16 + grp)*68;
            #pragma unroll
            for (int j = 0; j < 8; j++) {
                *(float2*)(drow + j*8 + tig*2)        = make_float2(acc[j][0], acc[j][1]);
                *(float2*)(drow + 8*68 + j*8 + tig*2) = make_float2(acc[j][2], acc[j][3]);
            }
            __syncthreads();

            // epilogue: bias + store fp32
            float* outp = (jm == 0) ? g_esrc : (jm == 1) ? g_edst : (jm == 2) ? g_Bh : g_xs;
            #pragma unroll
            for (int r = 0; r < 8; r++) {
                int row = ty*8 + r;
                int nrow = base + row;
                if (nrow < NN) {
                    int off = nrow*64 + tx*4;
                    float4 d = *(const float4*)(sD + row*68 + tx*4);
                    d.x += bb[jm].x; d.y += bb[jm].y; d.z += bb[jm].z; d.w += bb[jm].w;
                    *(float4*)&outp[off] = d;
                    if (jm == 0) {
                        *(float4*)&g_sums[off] = make_float4(0.f, 0.f, 0.f, 0.f);
                        *(float4*)&g_sumh[off] = make_float4(0.f, 0.f, 0.f, 0.f);
                    }
                }
            }
            __syncthreads();              // protect sD before next jm's stage
        }
    }
}

// ---------------- K2: edge kernel — mma.sync f16 GEMM + fused epilogue ------
// Structure unchanged from R13/R15 (175.6 us, occ 48%); sigmoid switched to
// tanh.approx (1 MUFU vs 2 + fewer alu) — epilogue is ~80% of issued instrs
// and sigmoid was ~half of its scalar work.
__global__ void __launch_bounds__(256, 4) k_edge(
    const float* __restrict__ ef, const int* __restrict__ src, const int* __restrict__ dst,
    const float* __restrict__ Weg, const float* __restrict__ beg)
{
    extern __shared__ char smem[];
    int*    sidx = (int*)(smem + SM_IDX);
    float*  sred = (float*)(smem + SM_SRED);
    __half* sW   = (__half*)(smem + SM_W);
    __half* sA   = (__half*)(smem + SM_A);
    __half* sD   = (__half*)(smem + SM_D);

    int tid = threadIdx.x;
    int wid = tid >> 5, lane = tid & 31;
    int tig = lane & 3, grp = lane >> 2;
    int tx = tid & 15, ty = tid >> 4;

    // W fill: packed so B frag (b0,b1) = one 8-byte load.
    for (int i = tid; i < 4096; i += 256) {
        int k = i >> 6, n = i & 63;
        int s = k >> 4, r = k & 15;
        int q = (r & 7) >> 1, hi = r >> 3, lo = r & 1;
        sW[n*72 + s*16 + q*4 + hi*2 + lo] = __float2half_rn(Weg[i]);
    }
    float4 bb = *(const float4*)(beg + tx*4);

    float ls[4] = {0.f,0.f,0.f,0.f};
    float lq[4] = {0.f,0.f,0.f,0.f};

    int nchunk = EE / 128;    // 6250
    for (int c = blockIdx.x; c < nchunk; c += gridDim.x) {
        int base = c * 128;
        __syncthreads();      // prev epilogue done (sA/sidx reuse)
        #pragma unroll
        for (int l = 0; l < 8; l++) {
            int idx = tid + l * 256;             // float4 index 0..2047
            int r = idx >> 4, c4 = (idx & 15) * 4;
            float4 v = *(const float4*)(ef + (base + r)*64 + c4);
            __half2 h0 = __floats2half2_rn(v.x, v.y);
            __half2 h1 = __floats2half2_rn(v.z, v.w);
            *(uint2*)(sA + r*72 + c4) = make_uint2(h2bits(h0), h2bits(h1));
        }
        if (tid < 128) sidx[tid] = src[base + tid];
        else           sidx[tid] = dst[base + tid - 128];
        __syncthreads();

        float acc[8][4];
        #pragma unroll
        for (int j = 0; j < 8; j++) {
            acc[j][0] = 0.f; acc[j][1] = 0.f; acc[j][2] = 0.f; acc[j][3] = 0.f;
        }

        const __half* arow = sA + (wid*16 + grp)*72;
        #pragma unroll
        for (int s = 0; s < 4; s++) {
            int k0 = s*16 + tig*2;
            uint32_t a0 = *(const uint32_t*)(arow + k0);
            uint32_t a1 = *(const uint32_t*)(arow + 8*72 + k0);
            uint32_t a2 = *(const uint32_t*)(arow + k0 + 8);
            uint32_t a3 = *(const uint32_t*)(arow + 8*72 + k0 + 8);
            #pragma unroll
            for (int j = 0; j < 8; j++) {
                uint2 b = *(const uint2*)(sW + (j*8 + grp)*72 + s*16 + tig*4);
                mma_16816(acc[j], a0, a1, a2, a3, b.x, b.y);
            }
        }

        // stage D to smem as fp16
        __half* drow = sD + (wid*16 + grp)*72;
        #pragma unroll
        for (int j = 0; j < 8; j++) {
            *(uint32_t*)(drow + j*8 + tig*2)        = h2bits(__floats2half2_rn(acc[j][0], acc[j][1]));
            *(uint32_t*)(drow + 8*72 + j*8 + tig*2) = h2bits(__floats2half2_rn(acc[j][2], acc[j][3]));
        }
        __syncthreads();

        // epilogue (R7 mapping: ty -> 8 rows, tx -> col quad)
        #pragma unroll
        for (int r = 0; r < 8; r++) {
            int row = ty*8 + r;
            int e = base + row;
            int s = sidx[row], t = sidx[128 + row];
            const int soff = s*64 + tx*4;
            const int toff = t*64 + tx*4;
            uint2 dpk = *(const uint2*)(sD + row*72 + tx*4);
            float2 d01 = __half22float2(*(__half2*)&dpk.x);
            float2 d23 = __half22float2(*(__half2*)&dpk.y);
            float4 es = *(const float4*)&g_esrc[soff];
            float4 ed = *(const float4*)&g_edst[toff];
            float4 m;
            m.x = d01.x + bb.x + es.x + ed.x;
            m.y = d01.y + bb.y + es.y + ed.y;
            m.z = d23.x + bb.z + es.z + ed.z;
            m.w = d23.y + bb.w + es.w + ed.w;

            __half2 h0 = __floats2half2_rn(m.x, m.y);
            __half2 h1 = __floats2half2_rn(m.z, m.w);
            *(uint2*)(g_mh + (size_t)e*64 + tx*4) = make_uint2(h2bits(h0), h2bits(h1));

            ls[0] += m.x; lq[0] += m.x*m.x;
            ls[1] += m.y; lq[1] += m.y*m.y;
            ls[2] += m.z; lq[2] += m.z*m.z;
            ls[3] += m.w; lq[3] += m.w*m.w;

            float4 bh = *(const float4*)&g_Bh[soff];
            float sg0 = fsigmoid_fast(m.x), sg1 = fsigmoid_fast(m.y);
            float sg2 = fsigmoid_fast(m.z), sg3 = fsigmoid_fast(m.w);
            red_add_v4(&g_sums[toff], sg0, sg1, sg2, sg3);
            red_add_v4(&g_sumh[toff], bh.x*sg0, bh.y*sg1, bh.z*sg2, bh.w*sg3);
        }
    }

    // block-level BN stats reduction: feature d = tx*4 + comp, reduce over ty
    #pragma unroll
    for (int comp = 0; comp < 4; comp++) {
        __syncthreads();
        sred[tid] = ls[comp];
        __syncthreads();
        if (ty == 0) {
            float ssum = 0.f;
            #pragma unroll
            for (int j = 0; j < 16; j++) ssum += sred[j*16 + tx];
            atomicAdd(&g_stats[tx*4 + comp], ssum);
        }
        __syncthreads();
        sred[tid] = lq[comp];
        __syncthreads();
        if (ty == 0) {
            float ssum = 0.f;
            #pragma unroll
            for (int j = 0; j < 16; j++) ssum += sred[j*16 + tx];
            atomicAdd(&g_stats[64 + tx*4 + comp], ssum);
        }
    }
}

// ---------------- K3: node finalize: x_pre = xs + h, node-BN stats -----------
// float4 + __fdividef (rcp.approx) — was instruction-latency-bound on IEEE div
__global__ void __launch_bounds__(256) k_node_fin() {
    int tid = threadIdx.x;
    int stride = gridDim.x * 256;          // in float4 units
    float ls[4] = {0.f,0.f,0.f,0.f};
    float lq[4] = {0.f,0.f,0.f,0.f};
    for (int q = blockIdx.x * 256 + tid; q < NN*DD/4; q += stride) {
        float4 sh_ = *(const float4*)&g_sumh[q*4];
        float4 ss  = *(const float4*)&g_sums[q*4];
        float4 xs  = *(const float4*)&g_xs[q*4];
        float4 xp;
        xp.x = xs.x + __fdividef(sh_.x, ss.x + 1e-6f);
        xp.y = xs.y + __fdividef(sh_.y, ss.y + 1e-6f);
        xp.z = xs.z + __fdividef(sh_.z, ss.z + 1e-6f);
        xp.w = xs.w + __fdividef(sh_.w, ss.w + 1e-6f);
        *(float4*)&g_xs[q*4] = xp;
        ls[0] += xp.x; lq[0] += xp.x*xp.x;
        ls[1] += xp.y; lq[1] += xp.y*xp.y;
        ls[2] += xp.z; lq[2] += xp.z*xp.z;
        ls[3] += xp.w; lq[3] += xp.w*xp.w;
    }
    // feature of component c = (q & 15)*4 + c ; tid & 15 is q's low bits
    __shared__ float sred[256];
    int tx = tid & 15, ty = tid >> 4;
    #pragma unroll
    for (int comp = 0; comp < 4; comp++) {
        __syncthreads();
        sred[tid] = ls[comp];
        __syncthreads();
        if (ty == 0) {
            float s = 0.f;
            #pragma unroll
            for (int j = 0; j < 16; j++) s += sred[j*16 + tx];
            atomicAdd(&g_stats[128 + tx*4 + comp], s);
        }
        __syncthreads();
        sred[tid] = lq[comp];
        __syncthreads();
        if (ty == 0) {
            float s = 0.f;
            #pragma unroll
            for (int j = 0; j < 16; j++) s += sred[j*16 + tx];
            atomicAdd(&g_stats[192 + tx*4 + comp], s);
        }
    }
}

// ---------------- K4: fused output (edge + node), BN params computed inline --
#define NEDGE8 (EE * 8)            // 6,400,000
__global__ void __launch_bounds__(256) k_output(
    const float* __restrict__ nf, const float* __restrict__ ef,
    const float* __restrict__ gn, const float* __restrict__ btn,
    const float* __restrict__ ge, const float* __restrict__ bte,
    float* __restrict__ out)
{
    __shared__ float sbn[256];   // [0:64) sc_n, [64:128) sh_n, [128:192) sc_e, [192:256) sh_e
    int tid = threadIdx.x;
    if (tid < 64) {
        float me = g_stats[tid] * (1.f / EE);
        float ve = g_stats[64 + tid] * (1.f / EE) - me * me;
        float se = ge[tid] * rsqrtf(ve + 1e-5f);
        sbn[128 + tid] = se;
        sbn[192 + tid] = bte[tid] - me * se;
        float mn = g_stats[128 + tid] * (1.f / NN);
        float vn = g_stats[192 + tid] * (1.f / NN) - mn * mn;
        float sn = gn[tid] * rsqrtf(vn + 1e-5f);
        sbn[tid]      = sn;
        sbn[64 + tid] = btn[tid] - mn * sn;
    }
    __syncthreads();

    int idx = blockIdx.x * 256 + tid;
    if (idx < NEDGE8) {
        // edge octet: 8 consecutive features
        int d8 = (idx & 7) * 8;
        size_t off = (size_t)idx * 8;
        uint4 pk = *(const uint4*)(g_mh + off);
        float2 m0 = __half22float2(*(__half2*)&pk.x);
        float2 m1 = __half22float2(*(__half2*)&pk.y);
        float2 m2 = __half22float2(*(__half2*)&pk.z);
        float2 m3 = __half22float2(*(__half2*)&pk.w);
        float4 sc0 = *(const float4*)&sbn[128 + d8];
        float4 sc1 = *(const float4*)&sbn[128 + d8 + 4];
        float4 sh0 = *(const float4*)&sbn[192 + d8];
        float4 sh1 = *(const float4*)&sbn[192 + d8 + 4];
        float4 e0 = *(const float4*)&ef[off];
        float4 e1 = *(const float4*)&ef[off + 4];
        float4 o0, o1;
        o0.x = e0.x + fsilu(m0.x*sc0.x + sh0.x);
        o0.y = e0.y + fsilu(m0.y*sc0.y + sh0.y);
        o0.z = e0.z + fsilu(m1.x*sc0.z + sh0.z);
        o0.w = e0.w + fsilu(m1.y*sc0.w + sh0.w);
        o1.x = e1.x + fsilu(m2.x*sc1.x + sh1.x);
        o1.y = e1.y + fsilu(m2.y*sc1.y + sh1.y);
        o1.z = e1.z + fsilu(m3.x*sc1.z + sh1.z);
        o1.w = e1.w + fsilu(m3.y*sc1.w + sh1.w);
        float* op = out + (size_t)NN*DD + off;
        *(float4*)op       = o0;
        *(float4*)(op + 4) = o1;
    } else {
        // node quad
        int i4 = idx - NEDGE8;           // [0, 800000)
        int d4 = (i4 & 15) * 4;
        float4 sc = *(const float4*)&sbn[d4];
        float4 sh = *(const float4*)&sbn[64 + d4];
        float4 xp = *(const float4*)&g_xs[i4*4];
        float4 bs = *(const float4*)&nf[i4*4];
        float4 o;
        o.x = bs.x + fsilu(xp.x*sc.x + sh.x);
        o.y = bs.y + fsilu(xp.y*sc.y + sh.y);
        o.z = bs.z + fsilu(xp.z*sc.z + sh.z);
        o.w = bs.w + fsilu(xp.w*sc.w + sh.w);
        *(float4*)&out[i4*4] = o;
    }
}

// ---------------- launcher ---------------------------------------------------
extern "C" void kernel_launch(void* const* d_in, const int* in_sizes, int n_in,
                              void* d_out, int out_size)
{
    const float* nf  = (const float*)d_in[0];
    const float* ef  = (const float*)d_in[1];
    const int*   src = (const int*)  d_in[2];
    const int*   dst = (const int*)  d_in[3];
    const float *Wsg = (const float*)d_in[4],  *bsg = (const float*)d_in[5];
    const float *Wdg = (const float*)d_in[6],  *bdg = (const float*)d_in[7];
    const float *Weg = (const float*)d_in[8],  *beg = (const float*)d_in[9];
    const float *Wsu = (const float*)d_in[10], *bsu = (const float*)d_in[11];
    const float *Wdu = (const float*)d_in[12], *bdu = (const float*)d_in[13];
    const float *gn  = (const float*)d_in[14], *btn = (const float*)d_in[15];
    const float *ge  = (const float*)d_in[16], *bte = (const float*)d_in[17];
    float* out = (float*)d_out;

    cudaFuncSetAttribute(k_node_gemm, cudaFuncAttributeMaxDynamicSharedMemorySize,
                         NG_TOTAL);
    cudaFuncSetAttribute(k_edge, cudaFuncAttributeMaxDynamicSharedMemorySize,
                         SM_EDGE_TOTAL);

    k_node_gemm<<<391, 256, NG_TOTAL>>>(nf, Wsg, bsg, Wdg, bdg,
                                        Wdu, bdu, Wsu, bsu);          // launch 0
    k_edge<<<2960, 256, SM_EDGE_TOTAL>>>(ef, src, dst, Weg, beg);     // launch 1
    k_node_fin<<<1024, 256>>>();                                      // launch 2
    k_output<<<28125, 256>>>(nf, ef, gn, btn, ge, bte, out);          // launch 3
}